// round 2
// baseline (speedup 1.0000x reference)
#include <cuda_runtime.h>
#include <math.h>

// ---------------- problem constants (fixed shapes) ----------------
#define Tt 8192            // tokens = B*S
#define Dd 1024            // model dim
#define Ee 8               // experts
#define Ff 4096            // ffn dim
#define TOPK 2

// ---------------- GEMM tiling ----------------
#define BM 64
#define BN 128
#define BK 16
#define CAPM (TOPK*Tt + Ee*BM)   // 16384 + 512 = 16896 padded pair rows
#define NMT  (CAPM/BM)           // 264 M-tiles

// ---------------- device scratch (static, allocation-free) ----------------
__device__ int   g_cnt[Ee];
__device__ int   g_rows_raw[Ee * Tt];
__device__ float g_wts_raw[Ee * Tt];
__device__ int   g_pair_row[CAPM];
__device__ float g_pair_wt[CAPM];
__device__ int   g_tile_expert[NMT];
__device__ float g_h[(size_t)CAPM * Ff];   // ~277 MB fp32 hidden scratch

// ---------------- helpers ----------------
__device__ __forceinline__ void ffma2(unsigned long long& d,
                                      unsigned long long a,
                                      unsigned long long b) {
    asm("fma.rn.f32x2 %0, %1, %2, %0;" : "+l"(d) : "l"(a), "l"(b));
}
__device__ __forceinline__ unsigned long long dup2(float a) {
    unsigned long long r;
    asm("mov.b64 %0, {%1, %1};" : "=l"(r) : "f"(a));
    return r;
}
__device__ __forceinline__ void unpack2(unsigned long long p, float& lo, float& hi) {
    asm("mov.b64 {%0, %1}, %2;" : "=f"(lo), "=f"(hi) : "l"(p));
}
__device__ __forceinline__ float gelu_exact(float c) {
    return 0.5f * c * (1.0f + erff(c * 0.70710678118654752f));
}

// ---------------- kernel 0: zero counters ----------------
__global__ void k_zero() {
    if (threadIdx.x < Ee) g_cnt[threadIdx.x] = 0;
}

// ---------------- kernel 1: router (1 warp per token) ----------------
__global__ void k_router(const float* __restrict__ x,
                         const float* __restrict__ gw) {
    int t = (blockIdx.x * blockDim.x + threadIdx.x) >> 5;
    int lane = threadIdx.x & 31;
    if (t >= Tt) return;
    const float* xr = x + (size_t)t * Dd;

    float acc[Ee];
#pragma unroll
    for (int e = 0; e < Ee; e++) acc[e] = 0.0f;

    for (int d = lane; d < Dd; d += 32) {
        float xv = __ldg(xr + d);
        const float4* g4 = (const float4*)(gw + (size_t)d * Ee);
        float4 glo = g4[0], ghi = g4[1];
        acc[0] += xv * glo.x; acc[1] += xv * glo.y;
        acc[2] += xv * glo.z; acc[3] += xv * glo.w;
        acc[4] += xv * ghi.x; acc[5] += xv * ghi.y;
        acc[6] += xv * ghi.z; acc[7] += xv * ghi.w;
    }
#pragma unroll
    for (int e = 0; e < Ee; e++) {
#pragma unroll
        for (int o = 16; o > 0; o >>= 1)
            acc[e] += __shfl_xor_sync(0xFFFFFFFFu, acc[e], o);
    }
    if (lane == 0) {
        int i0 = 0; float v0 = acc[0];
#pragma unroll
        for (int e = 1; e < Ee; e++) if (acc[e] > v0) { v0 = acc[e]; i0 = e; }
        int i1 = -1; float v1 = -3.402823466e38f;
#pragma unroll
        for (int e = 0; e < Ee; e++)
            if (e != i0 && acc[e] > v1) { v1 = acc[e]; i1 = e; }
        float ex = expf(v1 - v0);          // <= 1, stable
        float den = 1.0f + ex;
        float w0 = 1.0f / den;
        float w1 = ex / den;
        int p0 = atomicAdd(&g_cnt[i0], 1);
        g_rows_raw[i0 * Tt + p0] = t; g_wts_raw[i0 * Tt + p0] = w0;
        int p1 = atomicAdd(&g_cnt[i1], 1);
        g_rows_raw[i1 * Tt + p1] = t; g_wts_raw[i1 * Tt + p1] = w1;
    }
}

// ---------------- kernel 2: compact into padded segments ----------------
__global__ void k_compact() {
    __shared__ int start[Ee + 1];
    int tid = threadIdx.x;
    if (tid == 0) {
        int s = 0;
        for (int e = 0; e < Ee; e++) {
            start[e] = s;
            s += (g_cnt[e] + BM - 1) & ~(BM - 1);
        }
        start[Ee] = s;
    }
    __syncthreads();

    for (int e = 0; e < Ee; e++) {
        int c = g_cnt[e];
        int s = start[e];
        int padded = (c + BM - 1) & ~(BM - 1);
        for (int i = tid; i < padded; i += blockDim.x) {
            if (i < c) {
                g_pair_row[s + i] = g_rows_raw[e * Tt + i];
                g_pair_wt[s + i]  = g_wts_raw[e * Tt + i];
            } else {
                g_pair_row[s + i] = -1;
                g_pair_wt[s + i]  = 0.0f;
            }
        }
    }
    for (int i = start[Ee] + tid; i < CAPM; i += blockDim.x) {
        g_pair_row[i] = -1;
        g_pair_wt[i]  = 0.0f;
    }
    for (int m = tid; m < NMT; m += blockDim.x) {
        int base = m * BM;
        int e = Ee - 1;
        for (int j = 0; j < Ee; j++)
            if (base >= start[j] && base < start[j + 1]) { e = j; break; }
        g_tile_expert[m] = e;
    }
}

// ---------------- kernel 3: GEMM1  h = gelu(gather(x) @ w1[e] + b1[e]) ----------------
__global__ __launch_bounds__(256) void k_gemm1(const float* __restrict__ x,
                                               const float* __restrict__ w1,
                                               const float* __restrict__ b1) {
    __shared__ __align__(16) float As[BK][BM];
    __shared__ __align__(16) float Bs[BK][BN];
    __shared__ int rowIdx[BM];

    int tid   = threadIdx.x;
    int ntile = blockIdx.x;              // 0..Ff/BN-1
    int mtile = blockIdx.y;              // 0..NMT-1
    int e     = g_tile_expert[mtile];
    const float* Bp = w1 + (size_t)e * Dd * Ff + (size_t)ntile * BN;

    if (tid < BM) rowIdx[tid] = g_pair_row[mtile * BM + tid];
    __syncthreads();

    int am = tid >> 2;                   // row in tile for A load
    int ak = (tid & 3) << 2;             // k offset (float4)
    int arow = rowIdx[am];

    int tx = tid & 15, ty = tid >> 4;
    int m0 = ty * 4, n0 = tx * 8;

    unsigned long long acc[4][4];
#pragma unroll
    for (int i = 0; i < 4; i++)
#pragma unroll
        for (int j = 0; j < 4; j++) acc[i][j] = 0ull;

    int bk = tid >> 5;                   // 0..7
    int bn = (tid & 31) << 2;            // 0..124

    for (int k0 = 0; k0 < Dd; k0 += BK) {
        float4 av = make_float4(0.f, 0.f, 0.f, 0.f);
        if (arow >= 0)
            av = *(const float4*)(x + (size_t)arow * Dd + k0 + ak);
        float4 bv0 = *(const float4*)(Bp + (size_t)(k0 + bk) * Ff + bn);
        float4 bv1 = *(const float4*)(Bp + (size_t)(k0 + bk + 8) * Ff + bn);
        __syncthreads();
        As[ak + 0][am] = av.x; As[ak + 1][am] = av.y;
        As[ak + 2][am] = av.z; As[ak + 3][am] = av.w;
        *(float4*)&Bs[bk][bn]     = bv0;
        *(float4*)&Bs[bk + 8][bn] = bv1;
        __syncthreads();
#pragma unroll
        for (int k = 0; k < BK; k++) {
            float4 a4 = *(const float4*)&As[k][m0];
            ulonglong2 b01 = *(const ulonglong2*)&Bs[k][n0];
            ulonglong2 b23 = *(const ulonglong2*)&Bs[k][n0 + 4];
#define STEP1(i, aval)                                          \
            { unsigned long long ad = dup2(aval);               \
              ffma2(acc[i][0], ad, b01.x);                      \
              ffma2(acc[i][1], ad, b01.y);                      \
              ffma2(acc[i][2], ad, b23.x);                      \
              ffma2(acc[i][3], ad, b23.y); }
            STEP1(0, a4.x) STEP1(1, a4.y) STEP1(2, a4.z) STEP1(3, a4.w)
#undef STEP1
        }
    }

    // epilogue: +bias, exact GELU, store to g_h
    int gn0 = ntile * BN + n0;
    const float* b1p = b1 + (size_t)e * Ff + gn0;
    float bias[8];
#pragma unroll
    for (int j = 0; j < 8; j++) bias[j] = b1p[j];

    size_t hbase = (size_t)(mtile * BM) * Ff;
#pragma unroll
    for (int i = 0; i < 4; i++) {
        float v[8];
#pragma unroll
        for (int j2 = 0; j2 < 4; j2++)
            unpack2(acc[i][j2], v[2 * j2], v[2 * j2 + 1]);
#pragma unroll
        for (int j = 0; j < 8; j++)
            v[j] = gelu_exact(v[j] + bias[j]);
        float* hp = g_h + hbase + (size_t)(m0 + i) * Ff + gn0;
        *(float4*)hp       = make_float4(v[0], v[1], v[2], v[3]);
        *(float4*)(hp + 4) = make_float4(v[4], v[5], v[6], v[7]);
    }
}

// ---------------- kernel 4: GEMM2  out[token] += wt * (h @ w2[e] + b2[e]) ----------------
__global__ __launch_bounds__(256) void k_gemm2(const float* __restrict__ w2,
                                               const float* __restrict__ b2,
                                               float* __restrict__ out) {
    __shared__ __align__(16) float As[BK][BM];
    __shared__ __align__(16) float Bs[BK][BN];
    __shared__ int rowIdx[BM];

    int tid   = threadIdx.x;
    int ntile = blockIdx.x;              // 0..Dd/BN-1
    int mtile = blockIdx.y;              // 0..NMT-1
    int e     = g_tile_expert[mtile];
    const float* Bp = w2 + (size_t)e * Ff * Dd + (size_t)ntile * BN;
    const float* Ab = g_h + (size_t)(mtile * BM) * Ff;

    if (tid < BM) rowIdx[tid] = g_pair_row[mtile * BM + tid];
    __syncthreads();

    int am = tid >> 2;
    int ak = (tid & 3) << 2;

    int tx = tid & 15, ty = tid >> 4;
    int m0 = ty * 4, n0 = tx * 8;

    unsigned long long acc[4][4];
#pragma unroll
    for (int i = 0; i < 4; i++)
#pragma unroll
        for (int j = 0; j < 4; j++) acc[i][j] = 0ull;

    int bk = tid >> 5;
    int bn = (tid & 31) << 2;

    for (int k0 = 0; k0 < Ff; k0 += BK) {
        float4 av  = *(const float4*)(Ab + (size_t)am * Ff + k0 + ak);
        float4 bv0 = *(const float4*)(Bp + (size_t)(k0 + bk) * Dd + bn);
        float4 bv1 = *(const float4*)(Bp + (size_t)(k0 + bk + 8) * Dd + bn);
        __syncthreads();
        As[ak + 0][am] = av.x; As[ak + 1][am] = av.y;
        As[ak + 2][am] = av.z; As[ak + 3][am] = av.w;
        *(float4*)&Bs[bk][bn]     = bv0;
        *(float4*)&Bs[bk + 8][bn] = bv1;
        __syncthreads();
#pragma unroll
        for (int k = 0; k < BK; k++) {
            float4 a4 = *(const float4*)&As[k][m0];
            ulonglong2 b01 = *(const ulonglong2*)&Bs[k][n0];
            ulonglong2 b23 = *(const ulonglong2*)&Bs[k][n0 + 4];
#define STEP2(i, aval)                                          \
            { unsigned long long ad = dup2(aval);               \
              ffma2(acc[i][0], ad, b01.x);                      \
              ffma2(acc[i][1], ad, b01.y);                      \
              ffma2(acc[i][2], ad, b23.x);                      \
              ffma2(acc[i][3], ad, b23.y); }
            STEP2(0, a4.x) STEP2(1, a4.y) STEP2(2, a4.z) STEP2(3, a4.w)
#undef STEP2
        }
    }

    // epilogue: scaled scatter-add into out
    int gn0 = ntile * BN + n0;
    const float* b2p = b2 + (size_t)e * Dd + gn0;
    float bias[8];
#pragma unroll
    for (int j = 0; j < 8; j++) bias[j] = b2p[j];

#pragma unroll
    for (int i = 0; i < 4; i++) {
        int lm = m0 + i;
        int token = rowIdx[lm];
        if (token < 0) continue;
        float wt = g_pair_wt[mtile * BM + lm];
        float v[8];
#pragma unroll
        for (int j2 = 0; j2 < 4; j2++)
            unpack2(acc[i][j2], v[2 * j2], v[2 * j2 + 1]);
        float* op = out + (size_t)token * Dd + gn0;
#pragma unroll
        for (int j = 0; j < 8; j++)
            atomicAdd(&op[j], wt * (v[j] + bias[j]));
    }
}

// ---------------- launch ----------------
extern "C" void kernel_launch(void* const* d_in, const int* in_sizes, int n_in,
                              void* d_out, int out_size) {
    const float* x  = (const float*)d_in[0];   // [8192, 1024]
    const float* gw = (const float*)d_in[1];   // [1024, 8]
    const float* w1 = (const float*)d_in[2];   // [8, 1024, 4096]
    const float* b1 = (const float*)d_in[3];   // [8, 4096]
    const float* w2 = (const float*)d_in[4];   // [8, 4096, 1024]
    const float* b2 = (const float*)d_in[5];   // [8, 1024]
    float* out = (float*)d_out;                // [8192, 1024]

    cudaMemsetAsync(out, 0, (size_t)out_size * sizeof(float));
    k_zero<<<1, 32>>>();
    k_router<<<Tt / 8, 256>>>(x, gw);
    k_compact<<<1, 256>>>();
    k_gemm1<<<dim3(Ff / BN, NMT), 256>>>(x, w1, b1);
    k_gemm2<<<dim3(Dd / BN, NMT), 256>>>(w2, b2, out);
}

// round 9
// speedup vs baseline: 2.1972x; 2.1972x over previous
#include <cuda_runtime.h>
#include <cuda_bf16.h>
#include <math.h>
#include <stdint.h>

// ---------------- problem constants ----------------
#define Tt 8192
#define Dd 1024
#define Ee 8
#define Ff 4096
#define BM 128
#define BN 128
#define BK 32                    // k-chunk (elements)
#define CAPM (2*Tt + Ee*BM)      // 17408 padded pair rows
#define NMT  (CAPM/BM)           // 136 M-tiles

// ---------------- smem layout (bytes from dynamic base) ----------------
// fp32 staging (double buffered) + bf16 hi/lo converted tiles (single buffered)
#define SM_RI    0
#define SM_A32   1024
#define A32B     18432           // 128 rows * 36 floats * 4  (row stride 144B)
#define SM_B32   37888           // = 1024 + 2*A32B
#define B32B     16896           // 32 rows * 132 floats * 4  (row stride 528B)
#define SM_AHI   71680           // = SM_B32 + 2*B32B
#define A16B     10240           // 128 rows * 40 bf16 * 2    (row stride 80B)
#define SM_ALO   81920
#define SM_BHI   92160
#define B16B     8704            // 32 rows * 136 bf16 * 2    (row stride 272B)
#define SM_BLO  100864
#define SMEMSZ  109568

// ---------------- device scratch (kept small: ~273 MiB total) ----------------
__device__ int   g_cnt[Ee];
__device__ int   g_rows_raw[Ee*Tt];
__device__ float g_wts_raw[Ee*Tt];
__device__ int   g_pair_row[CAPM];
__device__ float g_pair_wt[CAPM];
__device__ int   g_tile_expert[NMT];
__device__ float g_h[(size_t)CAPM * Ff];     // 272 MiB fp32 hidden scratch

// ---------------- helpers ----------------
__device__ __forceinline__ uint32_t smem_u32(const void* p) {
    uint32_t a;
    asm("{ .reg .u64 t; cvta.to.shared.u64 t, %1; cvt.u32.u64 %0, t; }" : "=r"(a) : "l"(p));
    return a;
}
__device__ __forceinline__ void cp16(uint32_t dst, const void* src, uint32_t nbytes) {
    asm volatile("cp.async.cg.shared.global [%0], [%1], 16, %2;"
                 :: "r"(dst), "l"(src), "r"(nbytes) : "memory");
}
#define CP_COMMIT() asm volatile("cp.async.commit_group;" ::: "memory")
#define CP_WAIT(N)  asm volatile("cp.async.wait_group %0;" :: "n"(N) : "memory")

__device__ __forceinline__ void ldm_x4(uint32_t& r0, uint32_t& r1, uint32_t& r2, uint32_t& r3,
                                       uint32_t addr) {
    asm volatile("ldmatrix.sync.aligned.m8n8.x4.shared.b16 {%0,%1,%2,%3}, [%4];"
                 : "=r"(r0), "=r"(r1), "=r"(r2), "=r"(r3) : "r"(addr));
}
__device__ __forceinline__ void ldm_x4t(uint32_t& r0, uint32_t& r1, uint32_t& r2, uint32_t& r3,
                                        uint32_t addr) {
    asm volatile("ldmatrix.sync.aligned.m8n8.x4.trans.shared.b16 {%0,%1,%2,%3}, [%4];"
                 : "=r"(r0), "=r"(r1), "=r"(r2), "=r"(r3) : "r"(addr));
}
__device__ __forceinline__ void mma16816(float* d, const uint32_t* a, const uint32_t* b) {
    asm volatile("mma.sync.aligned.m16n8k16.row.col.f32.bf16.bf16.f32 "
                 "{%0,%1,%2,%3}, {%4,%5,%6,%7}, {%8,%9}, {%0,%1,%2,%3};"
                 : "+f"(d[0]), "+f"(d[1]), "+f"(d[2]), "+f"(d[3])
                 : "r"(a[0]), "r"(a[1]), "r"(a[2]), "r"(a[3]), "r"(b[0]), "r"(b[1]));
}
__device__ __forceinline__ float gelu_exact(float c) {
    return 0.5f * c * (1.0f + erff(c * 0.70710678118654752f));
}
__device__ __forceinline__ void split2(float a, float b, uint32_t& hi, uint32_t& lo) {
    __nv_bfloat16 h0 = __float2bfloat16(a), h1 = __float2bfloat16(b);
    __nv_bfloat16 l0 = __float2bfloat16(a - __bfloat162float(h0));
    __nv_bfloat16 l1 = __float2bfloat16(b - __bfloat162float(h1));
    hi = (uint32_t)__bfloat16_as_ushort(h0) | ((uint32_t)__bfloat16_as_ushort(h1) << 16);
    lo = (uint32_t)__bfloat16_as_ushort(l0) | ((uint32_t)__bfloat16_as_ushort(l1) << 16);
}

// ---------------- router / compact ----------------
__global__ void k_zero() { if (threadIdx.x < Ee) g_cnt[threadIdx.x] = 0; }

__global__ void k_router(const float* __restrict__ x, const float* __restrict__ gw) {
    int t = (blockIdx.x * blockDim.x + threadIdx.x) >> 5;
    int lane = threadIdx.x & 31;
    if (t >= Tt) return;
    const float* xr = x + (size_t)t * Dd;
    float acc[Ee];
#pragma unroll
    for (int e = 0; e < Ee; e++) acc[e] = 0.0f;
    for (int d = lane; d < Dd; d += 32) {
        float xv = __ldg(xr + d);
        const float4* g4 = (const float4*)(gw + (size_t)d * Ee);
        float4 glo = g4[0], ghi = g4[1];
        acc[0] += xv * glo.x; acc[1] += xv * glo.y;
        acc[2] += xv * glo.z; acc[3] += xv * glo.w;
        acc[4] += xv * ghi.x; acc[5] += xv * ghi.y;
        acc[6] += xv * ghi.z; acc[7] += xv * ghi.w;
    }
#pragma unroll
    for (int e = 0; e < Ee; e++)
#pragma unroll
        for (int o = 16; o > 0; o >>= 1)
            acc[e] += __shfl_xor_sync(0xFFFFFFFFu, acc[e], o);
    if (lane == 0) {
        int i0 = 0; float v0 = acc[0];
#pragma unroll
        for (int e = 1; e < Ee; e++) if (acc[e] > v0) { v0 = acc[e]; i0 = e; }
        int i1 = -1; float v1 = -3.402823466e38f;
#pragma unroll
        for (int e = 0; e < Ee; e++)
            if (e != i0 && acc[e] > v1) { v1 = acc[e]; i1 = e; }
        float ex = expf(v1 - v0);
        float den = 1.0f + ex;
        int p0 = atomicAdd(&g_cnt[i0], 1);
        g_rows_raw[i0 * Tt + p0] = t; g_wts_raw[i0 * Tt + p0] = 1.0f / den;
        int p1 = atomicAdd(&g_cnt[i1], 1);
        g_rows_raw[i1 * Tt + p1] = t; g_wts_raw[i1 * Tt + p1] = ex / den;
    }
}

__global__ void k_compact() {
    __shared__ int start[Ee + 1];
    int tid = threadIdx.x;
    if (tid == 0) {
        int s = 0;
        for (int e = 0; e < Ee; e++) { start[e] = s; s += (g_cnt[e] + BM - 1) & ~(BM - 1); }
        start[Ee] = s;
    }
    __syncthreads();
    for (int e = 0; e < Ee; e++) {
        int c = g_cnt[e], s = start[e];
        int padded = (c + BM - 1) & ~(BM - 1);
        for (int i = tid; i < padded; i += blockDim.x) {
            if (i < c) { g_pair_row[s + i] = g_rows_raw[e * Tt + i]; g_pair_wt[s + i] = g_wts_raw[e * Tt + i]; }
            else       { g_pair_row[s + i] = -1; g_pair_wt[s + i] = 0.0f; }
        }
    }
    for (int i = start[Ee] + tid; i < CAPM; i += blockDim.x) { g_pair_row[i] = -1; g_pair_wt[i] = 0.0f; }
    for (int m = tid; m < NMT; m += blockDim.x) {
        int base = m * BM, e = Ee - 1;
        for (int j = 0; j < Ee; j++)
            if (base >= start[j] && base < start[j + 1]) { e = j; break; }
        g_tile_expert[m] = e;
    }
}

// ---------------- stage load: fp32 A[128][32] (maybe gathered) + B[32][128] ----------------
__device__ __forceinline__ void load_stage(
    uint32_t smb, int buf, int tid, int k0,
    const float* __restrict__ Af, const int* rowIdxS, bool gather, size_t aRowBase, int ktot,
    const float* __restrict__ Bf, int ldb, int n0)
{
#pragma unroll
    for (int j = 0; j < 4; j++) {
        int c = j * 256 + tid;
        int r = c >> 3, o = c & 7;                 // 8 x 16B chunks per 128B row
        long row = gather ? (long)rowIdxS[r] : (long)(aRowBase + r);
        long srow = row >= 0 ? row : 0;
        uint32_t nb = row >= 0 ? 16u : 0u;         // zero-fill padded rows
        cp16(smb + SM_A32 + buf * A32B + r * 144 + o * 16,
             Af + (size_t)srow * ktot + k0 + o * 4, nb);
    }
#pragma unroll
    for (int j = 0; j < 4; j++) {
        int c = j * 256 + tid;
        int r = c >> 5, o = c & 31;                // 32 x 16B chunks per 512B row
        cp16(smb + SM_B32 + buf * B32B + r * 528 + o * 16,
             Bf + (size_t)(k0 + r) * ldb + n0 + o * 4, 16u);
    }
    CP_COMMIT();
}

// ---------------- convert fp32 stage -> bf16 hi/lo tiles ----------------
__device__ __forceinline__ void convert_stage(char* sm, int buf, int tid) {
    {   // A: 128x32, thread handles one half-row of 16 floats
        int row = tid >> 1, c0 = (tid & 1) * 16;
        const float* src = (const float*)(sm + SM_A32 + (size_t)buf * A32B) + row * 36 + c0;
        uint32_t hp[8], lp[8];
#pragma unroll
        for (int q = 0; q < 4; q++) {
            float4 v = *(const float4*)(src + q * 4);
            split2(v.x, v.y, hp[2*q],   lp[2*q]);
            split2(v.z, v.w, hp[2*q+1], lp[2*q+1]);
        }
        uint4* dh = (uint4*)((__nv_bfloat16*)(sm + SM_AHI) + row * 40 + c0);
        uint4* dl = (uint4*)((__nv_bfloat16*)(sm + SM_ALO) + row * 40 + c0);
        dh[0] = make_uint4(hp[0], hp[1], hp[2], hp[3]);
        dh[1] = make_uint4(hp[4], hp[5], hp[6], hp[7]);
        dl[0] = make_uint4(lp[0], lp[1], lp[2], lp[3]);
        dl[1] = make_uint4(lp[4], lp[5], lp[6], lp[7]);
    }
    {   // B: 32x128, thread handles 16 floats of one row
        int row = tid >> 3, c0 = (tid & 7) * 16;
        const float* src = (const float*)(sm + SM_B32 + (size_t)buf * B32B) + row * 132 + c0;
        uint32_t hp[8], lp[8];
#pragma unroll
        for (int q = 0; q < 4; q++) {
            float4 v = *(const float4*)(src + q * 4);
            split2(v.x, v.y, hp[2*q],   lp[2*q]);
            split2(v.z, v.w, hp[2*q+1], lp[2*q+1]);
        }
        uint4* dh = (uint4*)((__nv_bfloat16*)(sm + SM_BHI) + row * 136 + c0);
        uint4* dl = (uint4*)((__nv_bfloat16*)(sm + SM_BLO) + row * 136 + c0);
        dh[0] = make_uint4(hp[0], hp[1], hp[2], hp[3]);
        dh[1] = make_uint4(hp[4], hp[5], hp[6], hp[7]);
        dl[0] = make_uint4(lp[0], lp[1], lp[2], lp[3]);
        dl[1] = make_uint4(lp[4], lp[5], lp[6], lp[7]);
    }
}

// ---------------- warp MMA on converted tiles ----------------
__device__ __forceinline__ void compute_stage(uint32_t smb, int wid, int lane,
                                              float acc[4][4][4]) {
    int mwarp = (wid >> 2) * 64;
    int nwarp = (wid & 3) * 32;
#pragma unroll
    for (int ks = 0; ks < 2; ks++) {
        uint32_t ahi[4][4], alo[4][4];
        uint32_t koffA = (uint32_t)ks * 32 + (uint32_t)(lane >> 4) * 16;  // bytes in 80B row
        uint32_t rowA  = (uint32_t)(lane & 15);
#pragma unroll
        for (int mt = 0; mt < 4; mt++) {
            uint32_t ra = (uint32_t)(mwarp + mt * 16 + rowA) * 80 + koffA;
            ldm_x4(ahi[mt][0], ahi[mt][1], ahi[mt][2], ahi[mt][3], smb + SM_AHI + ra);
            ldm_x4(alo[mt][0], alo[mt][1], alo[mt][2], alo[mt][3], smb + SM_ALO + ra);
        }
        uint32_t bhi[4][2], blo[4][2];
        uint32_t rowB = (uint32_t)ks * 16 + (uint32_t)(lane & 15);
#pragma unroll
        for (int np = 0; np < 2; np++) {
            uint32_t rb = rowB * 272 + (uint32_t)(nwarp + np * 16 + ((lane >> 4) * 8)) * 2;
            uint32_t q0, q1, q2, q3;
            ldm_x4t(q0, q1, q2, q3, smb + SM_BHI + rb);
            bhi[2*np][0] = q0; bhi[2*np][1] = q1;
            bhi[2*np+1][0] = q2; bhi[2*np+1][1] = q3;
            ldm_x4t(q0, q1, q2, q3, smb + SM_BLO + rb);
            blo[2*np][0] = q0; blo[2*np][1] = q1;
            blo[2*np+1][0] = q2; blo[2*np+1][1] = q3;
        }
#pragma unroll
        for (int mt = 0; mt < 4; mt++)
#pragma unroll
            for (int nt = 0; nt < 4; nt++) {
                mma16816(acc[mt][nt], ahi[mt], bhi[nt]);
                mma16816(acc[mt][nt], ahi[mt], blo[nt]);
                mma16816(acc[mt][nt], alo[mt], bhi[nt]);
            }
    }
}

// ---------------- shared mainloop ----------------
__device__ __forceinline__ void gemm_main(
    char* sm, uint32_t smb, int tid, int wid, int lane, int nch,
    const float* __restrict__ Af, const int* rowIdxS, bool gather, size_t aRowBase, int ktot,
    const float* __restrict__ Bf, int ldb, int n0,
    float acc[4][4][4])
{
#pragma unroll
    for (int mt = 0; mt < 4; mt++)
#pragma unroll
        for (int nt = 0; nt < 4; nt++)
#pragma unroll
            for (int q = 0; q < 4; q++) acc[mt][nt][q] = 0.0f;

    load_stage(smb, 0, tid, 0, Af, rowIdxS, gather, aRowBase, ktot, Bf, ldb, n0);
    for (int i = 0; i < nch; i++) {
        if (i + 1 < nch) {
            load_stage(smb, (i + 1) & 1, tid, (i + 1) * BK,
                       Af, rowIdxS, gather, aRowBase, ktot, Bf, ldb, n0);
            CP_WAIT(1);
        } else {
            CP_WAIT(0);
        }
        __syncthreads();                 // fp32 stage i visible
        convert_stage(sm, i & 1, tid);
        __syncthreads();                 // bf16 tiles ready
        compute_stage(smb, wid, lane, acc);
        __syncthreads();                 // mma done before next convert overwrites
    }
}

// ---------------- GEMM1: g_h = gelu(gather(x) @ w1[e] + b1[e]) ----------------
__global__ __launch_bounds__(256, 1) void k_gemm1_mma(const float* __restrict__ x,
                                                      const float* __restrict__ w1,
                                                      const float* __restrict__ b1) {
    extern __shared__ char sm[];
    uint32_t smb = smem_u32(sm);
    int tid = threadIdx.x, wid = tid >> 5, lane = tid & 31;
    int ntile = blockIdx.x, mtile = blockIdx.y;
    int e = g_tile_expert[mtile];
    int* rowIdxS = (int*)(sm + SM_RI);
    if (tid < 128) rowIdxS[tid] = g_pair_row[mtile * 128 + tid];
    __syncthreads();

    float acc[4][4][4];
    const float* Bf = w1 + (size_t)e * Dd * Ff;     // [D][F], k=d rows, n=f cols
    gemm_main(sm, smb, tid, wid, lane, Dd / BK,
              x, rowIdxS, true, 0, Dd,
              Bf, Ff, ntile * BN, acc);

    int mwarp = (wid >> 2) * 64;
    int nwarp = (wid & 3) * 32;
    const float* bp = b1 + (size_t)e * Ff + (size_t)ntile * BN;
#pragma unroll
    for (int mt = 0; mt < 4; mt++) {
#pragma unroll
        for (int nt = 0; nt < 4; nt++) {
            int col = nwarp + nt * 8 + (lane & 3) * 2;
            float bb0 = bp[col], bb1 = bp[col + 1];
#pragma unroll
            for (int h = 0; h < 2; h++) {
                int r = mwarp + mt * 16 + (lane >> 2) + h * 8;
                float2 v;
                v.x = gelu_exact(acc[mt][nt][2*h]   + bb0);
                v.y = gelu_exact(acc[mt][nt][2*h+1] + bb1);
                *(float2*)(g_h + (size_t)(mtile * 128 + r) * Ff + (size_t)ntile * BN + col) = v;
            }
        }
    }
}

// ---------------- GEMM2: out[token] += wt * (g_h @ w2[e] + b2[e]) ----------------
__global__ __launch_bounds__(256, 1) void k_gemm2_mma(const float* __restrict__ w2,
                                                      const float* __restrict__ b2,
                                                      float* __restrict__ out) {
    extern __shared__ char sm[];
    uint32_t smb = smem_u32(sm);
    int tid = threadIdx.x, wid = tid >> 5, lane = tid & 31;
    int ntile = blockIdx.x, mtile = blockIdx.y;
    int e = g_tile_expert[mtile];
    int* rowIdxS = (int*)(sm + SM_RI);
    if (tid < 128) rowIdxS[tid] = g_pair_row[mtile * 128 + tid];
    __syncthreads();

    float acc[4][4][4];
    const float* Bf = w2 + (size_t)e * Ff * Dd;     // [F][D], k=f rows, n=d cols
    gemm_main(sm, smb, tid, wid, lane, Ff / BK,
              g_h, rowIdxS, false, (size_t)mtile * 128, Ff,
              Bf, Dd, ntile * BN, acc);

    int mwarp = (wid >> 2) * 64;
    int nwarp = (wid & 3) * 32;
    const float* bp = b2 + (size_t)e * Dd + (size_t)ntile * BN;
#pragma unroll
    for (int mt = 0; mt < 4; mt++) {
#pragma unroll
        for (int h = 0; h < 2; h++) {
            int r = mwarp + mt * 16 + (lane >> 2) + h * 8;
            int token = rowIdxS[r];
            if (token < 0) continue;
            float wt = g_pair_wt[mtile * 128 + r];
            float* op = out + (size_t)token * Dd + (size_t)ntile * BN;
#pragma unroll
            for (int nt = 0; nt < 4; nt++) {
                int col = nwarp + nt * 8 + (lane & 3) * 2;
                atomicAdd(op + col,     wt * (acc[mt][nt][2*h]   + bp[col]));
                atomicAdd(op + col + 1, wt * (acc[mt][nt][2*h+1] + bp[col + 1]));
            }
        }
    }
}

// ---------------- launch ----------------
extern "C" void kernel_launch(void* const* d_in, const int* in_sizes, int n_in,
                              void* d_out, int out_size) {
    const float* x  = (const float*)d_in[0];
    const float* gw = (const float*)d_in[1];
    const float* w1 = (const float*)d_in[2];
    const float* b1 = (const float*)d_in[3];
    const float* w2 = (const float*)d_in[4];
    const float* b2 = (const float*)d_in[5];
    float* out = (float*)d_out;

    cudaFuncSetAttribute(k_gemm1_mma, cudaFuncAttributeMaxDynamicSharedMemorySize, SMEMSZ);
    cudaFuncSetAttribute(k_gemm2_mma, cudaFuncAttributeMaxDynamicSharedMemorySize, SMEMSZ);

    cudaMemsetAsync(out, 0, (size_t)out_size * sizeof(float));
    k_zero<<<1, 32>>>();
    k_router<<<Tt / 8, 256>>>(x, gw);
    k_compact<<<1, 256>>>();
    k_gemm1_mma<<<dim3(Ff / BN, NMT), 256, SMEMSZ>>>(x, w1, b1);
    k_gemm2_mma<<<dim3(Dd / BN, NMT), 256, SMEMSZ>>>(w2, b2, out);
}